// round 11
// baseline (speedup 1.0000x reference)
#include <cuda_runtime.h>

#define T_LEN  1024
#define BATCH  512
#define HID    64

__device__ float g_hbuf[T_LEN * HID];

// ---- packed f32x2 + MUFU helpers (sm_103a) ----
__device__ __forceinline__ unsigned long long fma2(unsigned long long a,
                                                   unsigned long long b,
                                                   unsigned long long c) {
    unsigned long long d;
    asm("fma.rn.f32x2 %0, %1, %2, %3;" : "=l"(d) : "l"(a), "l"(b), "l"(c));
    return d;
}
__device__ __forceinline__ unsigned long long add2(unsigned long long a,
                                                   unsigned long long b) {
    unsigned long long d;
    asm("add.rn.f32x2 %0, %1, %2;" : "=l"(d) : "l"(a), "l"(b));
    return d;
}
__device__ __forceinline__ unsigned long long pack2(float lo, float hi) {
    unsigned long long d;
    asm("mov.b64 %0, {%1, %2};" : "=l"(d) : "f"(lo), "f"(hi));
    return d;
}
__device__ __forceinline__ float tanh_fast(float x) {
    float r; asm("tanh.approx.f32 %0, %1;" : "=f"(r) : "f"(x)); return r;
}

// 128 threads / 4 warps. Warp w, lane l: role = l>>4, unit u = w*16 + (l&15).
//   role 0 owns rows i (u), g (128+u)   -> produces i*g, sends via shfl
//   role 1 owns rows f (64+u), o (192+u) -> sole owner of c, h
// Sigmoid rows pre-scaled by 0.5: sigmoid = fma(.5, tanh(gate), .5).
__global__ void __launch_bounds__(128, 1)
lstm_seq_kernel(const float* __restrict__ x,
                const float* __restrict__ W_ih,
                const float* __restrict__ W_hh,
                const float* __restrict__ b_ih,
                const float* __restrict__ b_hh,
                const float* __restrict__ W_fc,
                const float* __restrict__ b_fc,
                float* __restrict__ out)
{
    __shared__ float x_s[T_LEN * 2];
    __shared__ __align__(16) float h_s[2][HID];

    const int tid  = threadIdx.x;
    const int w    = tid >> 5;
    const int l    = tid & 31;
    const int role = l >> 4;
    const int u    = (w << 4) | (l & 15);
    const int rA   = role ? (HID + u) : u;                  // i | f  (sigmoid)
    const int rB   = role ? (3 * HID + u) : (2 * HID + u);  // g (tanh) | o (sigmoid)

    for (int i = tid; i < T_LEN * 2; i += 128) {
        const int t = i >> 1, c = i & 1;
        x_s[i] = x[(t * BATCH + (BATCH - 1)) * 2 + c];
    }

    const float sclA = 0.5f;                   // i, f sigmoids
    const float sclB = role ? 0.5f : 1.0f;     // o sigmoid, g tanh
    ulonglong2 wA[16], wB[16];
    {
        const float4* pA = reinterpret_cast<const float4*>(W_hh + rA * HID);
        const float4* pB = reinterpret_cast<const float4*>(W_hh + rB * HID);
#pragma unroll
        for (int i = 0; i < 16; ++i) {
            const float4 a = pA[i];
            const float4 b = pB[i];
            wA[i].x = pack2(a.x * sclA, a.y * sclA);
            wA[i].y = pack2(a.z * sclA, a.w * sclA);
            wB[i].x = pack2(b.x * sclB, b.y * sclB);
            wB[i].y = pack2(b.z * sclB, b.w * sclB);
        }
    }

    const float bjA  = (b_ih[rA] + b_hh[rA]) * sclA;
    const float bjB  = (b_ih[rB] + b_hh[rB]) * sclB;
    const float wiA0 = W_ih[rA * 2] * sclA, wiA1 = W_ih[rA * 2 + 1] * sclA;
    const float wiB0 = W_ih[rB * 2] * sclB, wiB1 = W_ih[rB * 2 + 1] * sclB;

    const float bB = role ? 0.5f : 1.0f;   // role1 (o): sigmoid post-scale
    const float aB = role ? 0.5f : 0.0f;

    float c_state = 0.0f;                  // live only in role1
    if (tid < HID) h_s[0][tid] = 0.0f;
    __syncthreads();

#pragma unroll 1
    for (int t = 0; t < T_LEN; t += 2) {
#pragma unroll
        for (int ph = 0; ph < 2; ++ph) {
            const int tt = t + ph;
            const float2 xp = *reinterpret_cast<const float2*>(x_s + 2 * tt);
            const float gxA = fmaf(wiA0, xp.x, fmaf(wiA1, xp.y, bjA));
            const float gxB = fmaf(wiB0, xp.x, fmaf(wiB1, xp.y, bjB));

            const ulonglong2* hv = reinterpret_cast<const ulonglong2*>(h_s[ph]);

            // 2 accumulator chains per gate (4 total, rotating): same-chain
            // reissue every 4 instr * 2 cyc = 8 > 4-cyc FFMA2 latency.
            // Reduction tail shrinks to ONE add2 level per gate.
            unsigned long long aA0 = pack2(gxA, 0.0f), aA1 = 0ull;
            unsigned long long aB0 = pack2(gxB, 0.0f), aB1 = 0ull;
#pragma unroll
            for (int i = 0; i < 16; i += 2) {
                const ulonglong2 h0 = hv[i];
                const ulonglong2 h1 = hv[i + 1];
                aA0 = fma2(wA[i].x,     h0.x, aA0);
                aA1 = fma2(wA[i].y,     h0.y, aA1);
                aB0 = fma2(wB[i].x,     h0.x, aB0);
                aB1 = fma2(wB[i].y,     h0.y, aB1);
                aA0 = fma2(wA[i + 1].x, h1.x, aA0);
                aA1 = fma2(wA[i + 1].y, h1.y, aA1);
                aB0 = fma2(wB[i + 1].x, h1.x, aB0);
                aB1 = fma2(wB[i + 1].y, h1.y, aB1);
            }
            aA0 = add2(aA0, aA1);
            aB0 = add2(aB0, aB1);

            float loA, hiA, loB, hiB;
            asm("mov.b64 {%0, %1}, %2;" : "=f"(loA), "=f"(hiA) : "l"(aA0));
            asm("mov.b64 {%0, %1}, %2;" : "=f"(loB), "=f"(hiB) : "l"(aB0));

            const float gateA = loA + hiA;
            const float gateB = loB + hiB;

            const float thA = tanh_fast(gateA);   // i | f   (pre-scaled gates)
            const float thB = tanh_fast(gateB);   // g | pre-o

            // role0: send = i*g = (0.5+0.5*thA)*thB = fmaf(0.5*thB, thA, 0.5*thB).
            // The 0.5*thB mul overlaps thA's MUFU latency -> 1 fma after thA.
            const float mB   = 0.5f * thB;
            const float send = role ? 0.0f : fmaf(mB, thA, mB);
            const float recv = __shfl_xor_sync(0xffffffffu, send, 16);

            float h = 0.0f;
            if (role) {
                const float actA = fmaf(0.5f, thA, 0.5f);  // sigmoid(f)
                const float actB = fmaf(bB,   thB, aB);    // sigmoid(o)
                c_state = fmaf(actA, c_state, recv);       // f*c + i*g
                h = actB * tanh_fast(c_state);
                h_s[ph ^ 1][u] = h;
            }
            __syncthreads();
            if (role) g_hbuf[tt * HID + u] = h;   // post-barrier, off chain
        }
    }

    // ---- Fused FC tail: out[t,o] = W_fc[o].h_t + b_fc[o]  (2048 outputs) ----
    {
        const int o     = tid & 1;
        const int tbase = (tid >> 1) * 16;
        ulonglong2 wf[16];
        {
            const float4* wrow = reinterpret_cast<const float4*>(W_fc + o * HID);
#pragma unroll
            for (int i = 0; i < 16; ++i) {
                const float4 v = wrow[i];
                wf[i].x = pack2(v.x, v.y);
                wf[i].y = pack2(v.z, v.w);
            }
        }
        const float bias = b_fc[o];
#pragma unroll 1
        for (int k = 0; k < 16; ++k) {
            const int tt = tbase + k;
            const ulonglong2* hv =
                reinterpret_cast<const ulonglong2*>(g_hbuf + tt * HID);
            unsigned long long a0 = 0ull, a1 = 0ull, a2 = 0ull, a3 = 0ull;
#pragma unroll
            for (int i = 0; i < 16; i += 2) {
                const ulonglong2 h0 = hv[i];
                const ulonglong2 h1 = hv[i + 1];
                a0 = fma2(wf[i].x,     h0.x, a0);
                a1 = fma2(wf[i].y,     h0.y, a1);
                a2 = fma2(wf[i + 1].x, h1.x, a2);
                a3 = fma2(wf[i + 1].y, h1.y, a3);
            }
            a0 = add2(a0, a1); a2 = add2(a2, a3); a0 = add2(a0, a2);
            float lo, hi;
            asm("mov.b64 {%0, %1}, %2;" : "=f"(lo), "=f"(hi) : "l"(a0));
            out[tt * 2 + o] = (lo + hi) + bias;
        }
    }
}

extern "C" void kernel_launch(void* const* d_in, const int* in_sizes, int n_in,
                              void* d_out, int out_size)
{
    const float* x    = (const float*)d_in[0];
    const float* W_ih = (const float*)d_in[1];
    const float* W_hh = (const float*)d_in[2];
    const float* b_ih = (const float*)d_in[3];
    const float* b_hh = (const float*)d_in[4];
    const float* W_fc = (const float*)d_in[5];
    const float* b_fc = (const float*)d_in[6];
    float* out = (float*)d_out;

    lstm_seq_kernel<<<1, 128>>>(x, W_ih, W_hh, b_ih, b_hh, W_fc, b_fc, out);
}

// round 14
// speedup vs baseline: 1.0053x; 1.0053x over previous
#include <cuda_runtime.h>

#define T_LEN  1024
#define BATCH  512
#define HID    64

__device__ float g_hbuf[T_LEN * HID];

// ---- packed f32x2 + MUFU helpers (sm_103a) ----
__device__ __forceinline__ unsigned long long fma2(unsigned long long a,
                                                   unsigned long long b,
                                                   unsigned long long c) {
    unsigned long long d;
    asm("fma.rn.f32x2 %0, %1, %2, %3;" : "=l"(d) : "l"(a), "l"(b), "l"(c));
    return d;
}
__device__ __forceinline__ unsigned long long add2(unsigned long long a,
                                                   unsigned long long b) {
    unsigned long long d;
    asm("add.rn.f32x2 %0, %1, %2;" : "=l"(d) : "l"(a), "l"(b));
    return d;
}
__device__ __forceinline__ unsigned long long pack2(float lo, float hi) {
    unsigned long long d;
    asm("mov.b64 %0, {%1, %2};" : "=l"(d) : "f"(lo), "f"(hi));
    return d;
}
__device__ __forceinline__ float tanh_fast(float x) {
    float r; asm("tanh.approx.f32 %0, %1;" : "=f"(r) : "f"(x)); return r;
}

// 128 threads / 4 warps. Warp w, lane l: role = l>>4, unit u = w*16 + (l&15).
//   role 0 owns rows i (u), g (128+u)   -> produces i*g, sends via shfl
//   role 1 owns rows f (64+u), o (192+u) -> sole owner of valid c, h
// Sigmoid rows pre-scaled by 0.5: sigmoid = fma(.5, tanh(gate), .5).
// The c/h tail is BRANCHLESS: all lanes compute it (role0's values are
// garbage and unused); only the two stores are role-guarded so ptxas
// emits single @P-predicated STS/STG with no BSSY/BSYNC reconvergence.
__global__ void __launch_bounds__(128, 1)
lstm_seq_kernel(const float* __restrict__ x,
                const float* __restrict__ W_ih,
                const float* __restrict__ W_hh,
                const float* __restrict__ b_ih,
                const float* __restrict__ b_hh,
                const float* __restrict__ W_fc,
                const float* __restrict__ b_fc,
                float* __restrict__ out)
{
    __shared__ float x_s[T_LEN * 2];
    __shared__ __align__(16) float h_s[2][HID];

    const int tid  = threadIdx.x;
    const int w    = tid >> 5;
    const int l    = tid & 31;
    const int role = l >> 4;
    const int u    = (w << 4) | (l & 15);
    const int rA   = role ? (HID + u) : u;                  // i | f  (sigmoid)
    const int rB   = role ? (3 * HID + u) : (2 * HID + u);  // g (tanh) | o (sigmoid)

    for (int i = tid; i < T_LEN * 2; i += 128) {
        const int t = i >> 1, c = i & 1;
        x_s[i] = x[(t * BATCH + (BATCH - 1)) * 2 + c];
    }

    const float sclA = 0.5f;                   // i, f sigmoids
    const float sclB = role ? 0.5f : 1.0f;     // o sigmoid, g tanh
    ulonglong2 wA[16], wB[16];
    {
        const float4* pA = reinterpret_cast<const float4*>(W_hh + rA * HID);
        const float4* pB = reinterpret_cast<const float4*>(W_hh + rB * HID);
#pragma unroll
        for (int i = 0; i < 16; ++i) {
            const float4 a = pA[i];
            const float4 b = pB[i];
            wA[i].x = pack2(a.x * sclA, a.y * sclA);
            wA[i].y = pack2(a.z * sclA, a.w * sclA);
            wB[i].x = pack2(b.x * sclB, b.y * sclB);
            wB[i].y = pack2(b.z * sclB, b.w * sclB);
        }
    }

    const float bjA  = (b_ih[rA] + b_hh[rA]) * sclA;
    const float bjB  = (b_ih[rB] + b_hh[rB]) * sclB;
    const float wiA0 = W_ih[rA * 2] * sclA, wiA1 = W_ih[rA * 2 + 1] * sclA;
    const float wiB0 = W_ih[rB * 2] * sclB, wiB1 = W_ih[rB * 2 + 1] * sclB;

    const float bB = role ? 0.5f : 1.0f;   // role1 (o): sigmoid post-scale
    const float aB = role ? 0.5f : 0.0f;

    float c_state = 0.0f;                  // valid only in role1 lanes
    if (tid < HID) h_s[0][tid] = 0.0f;
    __syncthreads();

#pragma unroll 1
    for (int t = 0; t < T_LEN; t += 2) {
#pragma unroll
        for (int ph = 0; ph < 2; ++ph) {
            const int tt = t + ph;
            const float2 xp = *reinterpret_cast<const float2*>(x_s + 2 * tt);
            const float gxA = fmaf(wiA0, xp.x, fmaf(wiA1, xp.y, bjA));
            const float gxB = fmaf(wiB0, xp.x, fmaf(wiB1, xp.y, bjB));

            const ulonglong2* hv = reinterpret_cast<const ulonglong2*>(h_s[ph]);

            // 8 accumulator chains (best-measured structure, R10)
            unsigned long long aA0 = pack2(gxA, 0.0f), aA1 = 0ull, aA2 = 0ull, aA3 = 0ull;
            unsigned long long aB0 = pack2(gxB, 0.0f), aB1 = 0ull, aB2 = 0ull, aB3 = 0ull;
#pragma unroll
            for (int i = 0; i < 16; i += 2) {
                const ulonglong2 h0 = hv[i];
                const ulonglong2 h1 = hv[i + 1];
                aA0 = fma2(wA[i].x,     h0.x, aA0);
                aA1 = fma2(wA[i].y,     h0.y, aA1);
                aA2 = fma2(wA[i + 1].x, h1.x, aA2);
                aA3 = fma2(wA[i + 1].y, h1.y, aA3);
                aB0 = fma2(wB[i].x,     h0.x, aB0);
                aB1 = fma2(wB[i].y,     h0.y, aB1);
                aB2 = fma2(wB[i + 1].x, h1.x, aB2);
                aB3 = fma2(wB[i + 1].y, h1.y, aB3);
            }
            aA0 = add2(aA0, aA1); aA2 = add2(aA2, aA3); aA0 = add2(aA0, aA2);
            aB0 = add2(aB0, aB1); aB2 = add2(aB2, aB3); aB0 = add2(aB0, aB2);

            float loA, hiA, loB, hiB;
            asm("mov.b64 {%0, %1}, %2;" : "=f"(loA), "=f"(hiA) : "l"(aA0));
            asm("mov.b64 {%0, %1}, %2;" : "=f"(loB), "=f"(hiB) : "l"(aB0));

            const float gateA = loA + hiA;
            const float gateB = loB + hiB;

            const float actA = fmaf(0.5f, tanh_fast(gateA), 0.5f);  // i | f
            const float thB  = tanh_fast(gateB);                    // g | pre-o

            // role0 sends i*g; role1's send value is ignored
            const float send = role ? 0.0f : thB * actA;
            const float recv = __shfl_xor_sync(0xffffffffu, send, 16);

            // Branchless tail: all lanes compute; role0's results are unused.
            const float actB = fmaf(bB, thB, aB);      // sigmoid(o) in role1
            c_state = fmaf(actA, c_state, recv);       // f*c + i*g   in role1
            const float h = actB * tanh_fast(c_state);

            if (role) h_s[ph ^ 1][u] = h;              // single @P STS
            __syncthreads();
            if (role) g_hbuf[tt * HID + u] = h;        // single @P STG, off chain
        }
    }

    // ---- Fused FC tail: out[t,o] = W_fc[o].h_t + b_fc[o]  (2048 outputs) ----
    {
        const int o     = tid & 1;
        const int tbase = (tid >> 1) * 16;
        ulonglong2 wf[16];
        {
            const float4* wrow = reinterpret_cast<const float4*>(W_fc + o * HID);
#pragma unroll
            for (int i = 0; i < 16; ++i) {
                const float4 v = wrow[i];
                wf[i].x = pack2(v.x, v.y);
                wf[i].y = pack2(v.z, v.w);
            }
        }
        const float bias = b_fc[o];
#pragma unroll 1
        for (int k = 0; k < 16; ++k) {
            const int tt = tbase + k;
            const ulonglong2* hv =
                reinterpret_cast<const ulonglong2*>(g_hbuf + tt * HID);
            unsigned long long a0 = 0ull, a1 = 0ull, a2 = 0ull, a3 = 0ull;
#pragma unroll
            for (int i = 0; i < 16; i += 2) {
                const ulonglong2 h0 = hv[i];
                const ulonglong2 h1 = hv[i + 1];
                a0 = fma2(wf[i].x,     h0.x, a0);
                a1 = fma2(wf[i].y,     h0.y, a1);
                a2 = fma2(wf[i + 1].x, h1.x, a2);
                a3 = fma2(wf[i + 1].y, h1.y, a3);
            }
            a0 = add2(a0, a1); a2 = add2(a2, a3); a0 = add2(a0, a2);
            float lo, hi;
            asm("mov.b64 {%0, %1}, %2;" : "=f"(lo), "=f"(hi) : "l"(a0));
            out[tt * 2 + o] = (lo + hi) + bias;
        }
    }
}

extern "C" void kernel_launch(void* const* d_in, const int* in_sizes, int n_in,
                              void* d_out, int out_size)
{
    const float* x    = (const float*)d_in[0];
    const float* W_ih = (const float*)d_in[1];
    const float* W_hh = (const float*)d_in[2];
    const float* b_ih = (const float*)d_in[3];
    const float* b_hh = (const float*)d_in[4];
    const float* W_fc = (const float*)d_in[5];
    const float* b_fc = (const float*)d_in[6];
    float* out = (float*)d_out;

    lstm_seq_kernel<<<1, 128>>>(x, W_ih, W_hh, b_ih, b_hh, W_fc, b_fc, out);
}

// round 16
// speedup vs baseline: 1.0344x; 1.0290x over previous
#include <cuda_runtime.h>

#define T_LEN  1024
#define BATCH  512
#define HID    64

__device__ float g_hbuf[T_LEN * HID];

// ---- packed f32x2 + MUFU helpers (sm_103a) ----
__device__ __forceinline__ unsigned long long fma2(unsigned long long a,
                                                   unsigned long long b,
                                                   unsigned long long c) {
    unsigned long long d;
    asm("fma.rn.f32x2 %0, %1, %2, %3;" : "=l"(d) : "l"(a), "l"(b), "l"(c));
    return d;
}
__device__ __forceinline__ unsigned long long add2(unsigned long long a,
                                                   unsigned long long b) {
    unsigned long long d;
    asm("add.rn.f32x2 %0, %1, %2;" : "=l"(d) : "l"(a), "l"(b));
    return d;
}
__device__ __forceinline__ unsigned long long pack2(float lo, float hi) {
    unsigned long long d;
    asm("mov.b64 %0, {%1, %2};" : "=l"(d) : "f"(lo), "f"(hi));
    return d;
}
__device__ __forceinline__ float unpack_add(unsigned long long v) {
    float lo, hi;
    asm("mov.b64 {%0, %1}, %2;" : "=f"(lo), "=f"(hi) : "l"(v));
    return lo + hi;
}
__device__ __forceinline__ float tanh_fast(float x) {
    float r; asm("tanh.approx.f32 %0, %1;" : "=f"(r) : "f"(x)); return r;
}

// Split-K layout: 128 threads / 4 warps. Warp w, lane l:
//   kh = l>>4  : which 32-float half of h this lane owns
//   u  = w*16 + (l&15) : hidden unit
// Each lane computes PARTIAL dots of ALL FOUR gate rows (i,f,g,o) of unit u
// over its h-half (8 LDS.128 instead of 16). The lane pair exchanges 4 partial
// sums with 4 independent shfl_xor(16); afterwards every lane holds all four
// full gates -> no activation shuffle on the critical chain. Both lanes of a
// pair maintain c redundantly (bit-identical: add(own,recv) is commutative).
// Sigmoid rows (i,f,o) pre-scaled by 0.5: sigmoid = fma(.5, tanh(gate), .5).
// h_s halves are stored 36 floats (144 B) apart so the two per-warp address
// streams hit disjoint banks -> one wavefront per LDS.128.
__global__ void __launch_bounds__(128, 1)
lstm_seq_kernel(const float* __restrict__ x,
                const float* __restrict__ W_ih,
                const float* __restrict__ W_hh,
                const float* __restrict__ b_ih,
                const float* __restrict__ b_hh,
                const float* __restrict__ W_fc,
                const float* __restrict__ b_fc,
                float* __restrict__ out)
{
    __shared__ float x_s[T_LEN * 2];
    __shared__ __align__(16) float h_s[2][72];   // [0:32) h-lo, [36:68) h-hi

    const int tid = threadIdx.x;
    const int w   = tid >> 5;
    const int l   = tid & 31;
    const int kh  = l >> 4;                // h-half owned by this lane
    const int u   = (w << 4) | (l & 15);   // hidden unit 0..63

    const int rI = u;
    const int rF = HID + u;
    const int rG = 2 * HID + u;
    const int rO = 3 * HID + u;

    for (int i = tid; i < T_LEN * 2; i += 128) {
        const int t = i >> 1, c = i & 1;
        x_s[i] = x[(t * BATCH + (BATCH - 1)) * 2 + c];
    }

    // Weight half-rows (32 floats each), packed f32x2, sigmoid rows pre-scaled
    ulonglong2 wI[8], wF[8], wG[8], wO[8];
    {
        const float4* pI = reinterpret_cast<const float4*>(W_hh + rI * HID + kh * 32);
        const float4* pF = reinterpret_cast<const float4*>(W_hh + rF * HID + kh * 32);
        const float4* pG = reinterpret_cast<const float4*>(W_hh + rG * HID + kh * 32);
        const float4* pO = reinterpret_cast<const float4*>(W_hh + rO * HID + kh * 32);
#pragma unroll
        for (int i = 0; i < 8; ++i) {
            const float4 a = pI[i], b = pF[i], g = pG[i], o = pO[i];
            wI[i].x = pack2(a.x * 0.5f, a.y * 0.5f);
            wI[i].y = pack2(a.z * 0.5f, a.w * 0.5f);
            wF[i].x = pack2(b.x * 0.5f, b.y * 0.5f);
            wF[i].y = pack2(b.z * 0.5f, b.w * 0.5f);
            wG[i].x = pack2(g.x, g.y);
            wG[i].y = pack2(g.z, g.w);
            wO[i].x = pack2(o.x * 0.5f, o.y * 0.5f);
            wO[i].y = pack2(o.z * 0.5f, o.w * 0.5f);
        }
    }

    // x-term split across the pair: kh=0 contributes w0*x0, kh=1 w1*x1 + bias
    const float axI = W_ih[rI * 2 + kh] * 0.5f;
    const float axF = W_ih[rF * 2 + kh] * 0.5f;
    const float axG = W_ih[rG * 2 + kh];
    const float axO = W_ih[rO * 2 + kh] * 0.5f;
    const float bxI = kh ? (b_ih[rI] + b_hh[rI]) * 0.5f : 0.0f;
    const float bxF = kh ? (b_ih[rF] + b_hh[rF]) * 0.5f : 0.0f;
    const float bxG = kh ? (b_ih[rG] + b_hh[rG])        : 0.0f;
    const float bxO = kh ? (b_ih[rO] + b_hh[rO]) * 0.5f : 0.0f;

    float c_state = 0.0f;
    if (tid < 72) h_s[0][tid] = 0.0f;
    __syncthreads();

#pragma unroll 1
    for (int t = 0; t < T_LEN; t += 2) {
#pragma unroll
        for (int ph = 0; ph < 2; ++ph) {
            const int tt = t + ph;
            const float xk = x_s[2 * tt + kh];
            const float gxI = fmaf(axI, xk, bxI);
            const float gxF = fmaf(axF, xk, bxF);
            const float gxG = fmaf(axG, xk, bxG);
            const float gxO = fmaf(axO, xk, bxO);

            const ulonglong2* hv =
                reinterpret_cast<const ulonglong2*>(h_s[ph] + kh * 36);

            // 8 accumulator chains (2 per gate row)
            unsigned long long aI0 = pack2(gxI, 0.0f), aI1 = 0ull;
            unsigned long long aF0 = pack2(gxF, 0.0f), aF1 = 0ull;
            unsigned long long aG0 = pack2(gxG, 0.0f), aG1 = 0ull;
            unsigned long long aO0 = pack2(gxO, 0.0f), aO1 = 0ull;
#pragma unroll
            for (int i = 0; i < 8; ++i) {
                const ulonglong2 hc = hv[i];
                aI0 = fma2(wI[i].x, hc.x, aI0);
                aI1 = fma2(wI[i].y, hc.y, aI1);
                aF0 = fma2(wF[i].x, hc.x, aF0);
                aF1 = fma2(wF[i].y, hc.y, aF1);
                aG0 = fma2(wG[i].x, hc.x, aG0);
                aG1 = fma2(wG[i].y, hc.y, aG1);
                aO0 = fma2(wO[i].x, hc.x, aO0);
                aO1 = fma2(wO[i].y, hc.y, aO1);
            }
            const float pI = unpack_add(add2(aI0, aI1));
            const float pF = unpack_add(add2(aF0, aF1));
            const float pG = unpack_add(add2(aG0, aG1));
            const float pO = unpack_add(add2(aO0, aO1));

            // 4 independent partial-sum exchanges (overlap each other)
            const float qI = __shfl_xor_sync(0xffffffffu, pI, 16);
            const float qF = __shfl_xor_sync(0xffffffffu, pF, 16);
            const float qG = __shfl_xor_sync(0xffffffffu, pG, 16);
            const float qO = __shfl_xor_sync(0xffffffffu, pO, 16);

            const float gI = pI + qI;   // commutative add -> bit-identical in pair
            const float gF = pF + qF;
            const float gG = pG + qG;
            const float gO = pO + qO;

            // All gates lane-local now; 4 independent MUFUs
            const float thG = tanh_fast(gG);
            const float thI = tanh_fast(gI);
            const float thF = tanh_fast(gF);
            const float thO = tanh_fast(gO);

            const float i_ = fmaf(0.5f, thI, 0.5f);
            const float f_ = fmaf(0.5f, thF, 0.5f);
            const float o_ = fmaf(0.5f, thO, 0.5f);

            c_state = fmaf(f_, c_state, i_ * thG);
            const float h = o_ * tanh_fast(c_state);

            const int su = u + ((u >> 5) << 2);   // +4-float pad for hi half
            if (!kh) h_s[ph ^ 1][su] = h;         // single @P STS
            __syncthreads();
            if (!kh) g_hbuf[tt * HID + u] = h;    // single @P STG, off chain
        }
    }

    // ---- Fused FC tail: out[t,o] = W_fc[o].h_t + b_fc[o]  (2048 outputs) ----
    {
        const int o     = tid & 1;
        const int tbase = (tid >> 1) * 16;
        ulonglong2 wf[16];
        {
            const float4* wrow = reinterpret_cast<const float4*>(W_fc + o * HID);
#pragma unroll
            for (int i = 0; i < 16; ++i) {
                const float4 v = wrow[i];
                wf[i].x = pack2(v.x, v.y);
                wf[i].y = pack2(v.z, v.w);
            }
        }
        const float bias = b_fc[o];
#pragma unroll 1
        for (int k = 0; k < 16; ++k) {
            const int tt = tbase + k;
            const ulonglong2* hv =
                reinterpret_cast<const ulonglong2*>(g_hbuf + tt * HID);
            unsigned long long a0 = 0ull, a1 = 0ull, a2 = 0ull, a3 = 0ull;
#pragma unroll
            for (int i = 0; i < 16; i += 2) {
                const ulonglong2 h0 = hv[i];
                const ulonglong2 h1 = hv[i + 1];
                a0 = fma2(wf[i].x,     h0.x, a0);
                a1 = fma2(wf[i].y,     h0.y, a1);
                a2 = fma2(wf[i + 1].x, h1.x, a2);
                a3 = fma2(wf[i + 1].y, h1.y, a3);
            }
            a0 = add2(a0, a1); a2 = add2(a2, a3); a0 = add2(a0, a2);
            out[tt * 2 + o] = unpack_add(a0) + bias;
        }
    }
}

extern "C" void kernel_launch(void* const* d_in, const int* in_sizes, int n_in,
                              void* d_out, int out_size)
{
    const float* x    = (const float*)d_in[0];
    const float* W_ih = (const float*)d_in[1];
    const float* W_hh = (const float*)d_in[2];
    const float* b_ih = (const float*)d_in[3];
    const float* b_hh = (const float*)d_in[4];
    const float* W_fc = (const float*)d_in[5];
    const float* b_fc = (const float*)d_in[6];
    float* out = (float*)d_out;

    lstm_seq_kernel<<<1, 128>>>(x, W_ih, W_hh, b_ih, b_hh, W_fc, b_fc, out);
}